// round 5
// baseline (speedup 1.0000x reference)
#include <cuda_runtime.h>
#include <cstdint>

#define N_NODES 100000
#define N_EDGES 3200000
#define D_FEAT  128
#define HIDDEN  16
#define NCLS    7
#define H2PAD   8   // padded layer-2 width (7 -> 8) for float4 ops

// ---- scratch (static __device__ arrays; no allocation allowed) ----
__device__ float d_deg [N_NODES];                 // weighted degree (incl. self-loop)
__device__ float d_dinv[N_NODES];                 // rsqrt(deg), produced by gemm1
__device__ float d_g1  [N_NODES * HIDDEN];
__device__ float d_acc1[N_NODES * HIDDEN];
__device__ float d_g2  [N_NODES * H2PAD];
__device__ float d_acc2[N_NODES * H2PAD];

// vector reduction: 4 floats, one L2 atomic op
__device__ __forceinline__ void red_v4(float* p, float a, float b, float c, float d) {
    unsigned long long gp = __cvta_generic_to_global(p);
    asm volatile("red.global.v4.f32.add [%0], {%1,%2,%3,%4};"
                 :: "l"(gp), "f"(a), "f"(b), "f"(c), "f"(d) : "memory");
}

// ---------------- degree ----------------
__global__ void k_deg_init() {
    int n = blockIdx.x * blockDim.x + threadIdx.x;
    if (n < N_NODES) d_deg[n] = 1.0f;   // self-loop weight
}

__global__ void k_deg_acc(const int* __restrict__ ei,
                          const float* __restrict__ ew) {
    int e = blockIdx.x * blockDim.x + threadIdx.x;
    if (e >= N_EDGES) return;
    atomicAdd(&d_deg[ei[N_EDGES + e]], ew[e]);
}

// ---------------- layer 1 projection: g1 = (x @ W1) * dinv ----------------
// Block = 256 threads = 256 nodes. x staged through smem, fully coalesced.
#define KCHUNK 16
__global__ void __launch_bounds__(256) k_gemm1(const float* __restrict__ x,
                                               const float* __restrict__ W1) {
    __shared__ float sW[D_FEAT * HIDDEN];          // 8 KB
    __shared__ float sx[256][KCHUNK + 1];          // 17.4 KB, pad -> conflict-free
    for (int i = threadIdx.x; i < D_FEAT * HIDDEN; i += blockDim.x)
        sW[i] = W1[i];

    int tid = threadIdx.x;
    int n0 = blockIdx.x * 256;
    int n  = n0 + tid;
    int nrows = min(256, N_NODES - n0);            // rows this block owns

    float acc[HIDDEN];
#pragma unroll
    for (int j = 0; j < HIDDEN; j++) acc[j] = 0.0f;

    for (int c = 0; c < D_FEAT / KCHUNK; c++) {
        __syncthreads();
        int nvec = nrows * (KCHUNK / 4);           // float4 count
        for (int idx = tid; idx < nvec; idx += 256) {
            int r = idx >> 2;                      // KCHUNK/4 = 4 vecs per row
            int q = idx & 3;
            float4 v = *(const float4*)(x + (size_t)(n0 + r) * D_FEAT + c * KCHUNK + q * 4);
            sx[r][q * 4 + 0] = v.x;
            sx[r][q * 4 + 1] = v.y;
            sx[r][q * 4 + 2] = v.z;
            sx[r][q * 4 + 3] = v.w;
        }
        __syncthreads();
        if (n < N_NODES) {
#pragma unroll
            for (int kk = 0; kk < KCHUNK; kk++) {
                float v = sx[tid][kk];
                const float* wrow = &sW[(c * KCHUNK + kk) * HIDDEN];
#pragma unroll
                for (int j = 0; j < HIDDEN; j++)
                    acc[j] = fmaf(v, wrow[j], acc[j]);
            }
        }
    }

    if (n >= N_NODES) return;
    float di = rsqrtf(d_deg[n]);
    d_dinv[n] = di;
    float4* g = (float4*)(d_g1  + (size_t)n * HIDDEN);
    float4* a = (float4*)(d_acc1 + (size_t)n * HIDDEN);
#pragma unroll
    for (int q = 0; q < 4; q++) {
        float4 v = make_float4(acc[q*4+0]*di, acc[q*4+1]*di,
                               acc[q*4+2]*di, acc[q*4+3]*di);
        g[q] = v;   // message source values (pre-scaled by dinv[src])
        a[q] = v;   // accumulator initialized with self-loop term
    }
}

// ---------------- edge scatter, layer 1: 4 lanes per edge ----------------
__global__ void k_edge1(const int* __restrict__ ei,
                        const float* __restrict__ ew) {
    int t = blockIdx.x * blockDim.x + threadIdx.x;
    int e = t >> 2;
    int q = t & 3;
    if (e >= N_EDGES) return;
    int src = ei[e];                 // broadcast across the 4 lanes of this edge
    int dst = ei[N_EDGES + e];
    float w = ew[e];
    float4 v = *(const float4*)(d_g1 + (size_t)src * HIDDEN + q * 4);
    red_v4(d_acc1 + (size_t)dst * HIDDEN + q * 4, v.x * w, v.y * w, v.z * w, v.w * w);
}

// ---------------- layer-1 epilogue + layer-2 projection ----------------
__global__ void k_layer2(const float* __restrict__ b1,
                         const float* __restrict__ W2) {
    __shared__ float sW[HIDDEN * NCLS];
    __shared__ float sb1[HIDDEN];
    if (threadIdx.x < HIDDEN * NCLS) sW[threadIdx.x] = W2[threadIdx.x];
    if (threadIdx.x < HIDDEN)        sb1[threadIdx.x] = b1[threadIdx.x];
    __syncthreads();

    int n = blockIdx.x * blockDim.x + threadIdx.x;
    if (n >= N_NODES) return;

    float di = d_dinv[n];
    float h[HIDDEN];
    const float4* a = (const float4*)(d_acc1 + (size_t)n * HIDDEN);
#pragma unroll
    for (int q = 0; q < 4; q++) {
        float4 v = a[q];
        h[q*4+0] = fmaxf(v.x * di + sb1[q*4+0], 0.0f);
        h[q*4+1] = fmaxf(v.y * di + sb1[q*4+1], 0.0f);
        h[q*4+2] = fmaxf(v.z * di + sb1[q*4+2], 0.0f);
        h[q*4+3] = fmaxf(v.w * di + sb1[q*4+3], 0.0f);
    }

    float o[H2PAD];
#pragma unroll
    for (int c = 0; c < H2PAD; c++) o[c] = 0.0f;   // o[7] stays exactly 0
#pragma unroll
    for (int j = 0; j < HIDDEN; j++) {
#pragma unroll
        for (int c = 0; c < NCLS; c++)
            o[c] = fmaf(h[j], sW[j * NCLS + c], o[c]);
    }

    float4* g  = (float4*)(d_g2  + (size_t)n * H2PAD);
    float4* ac = (float4*)(d_acc2 + (size_t)n * H2PAD);
#pragma unroll
    for (int q = 0; q < 2; q++) {
        float4 v = make_float4(o[q*4+0]*di, o[q*4+1]*di, o[q*4+2]*di, o[q*4+3]*di);
        g[q] = v;
        ac[q] = v;
    }
}

// ---------------- edge scatter, layer 2: 2 lanes per edge ----------------
__global__ void k_edge2(const int* __restrict__ ei,
                        const float* __restrict__ ew) {
    int t = blockIdx.x * blockDim.x + threadIdx.x;
    int e = t >> 1;
    int q = t & 1;
    if (e >= N_EDGES) return;
    int src = ei[e];
    int dst = ei[N_EDGES + e];
    float w = ew[e];
    float4 v = *(const float4*)(d_g2 + (size_t)src * H2PAD + q * 4);
    red_v4(d_acc2 + (size_t)dst * H2PAD + q * 4, v.x * w, v.y * w, v.z * w, v.w * w);
}

// ---------------- layer-2 epilogue: log_softmax ----------------
__global__ void k_out(const float* __restrict__ b2,
                      float* __restrict__ out) {
    int n = blockIdx.x * blockDim.x + threadIdx.x;
    if (n >= N_NODES) return;
    float di = d_dinv[n];
    float v[NCLS];
    const float4* a = (const float4*)(d_acc2 + (size_t)n * H2PAD);
    float4 p0 = a[0], p1 = a[1];
    v[0] = p0.x * di + b2[0];
    v[1] = p0.y * di + b2[1];
    v[2] = p0.z * di + b2[2];
    v[3] = p0.w * di + b2[3];
    v[4] = p1.x * di + b2[4];
    v[5] = p1.y * di + b2[5];
    v[6] = p1.z * di + b2[6];
    float m = v[0];
#pragma unroll
    for (int c = 1; c < NCLS; c++) m = fmaxf(m, v[c]);
    float s = 0.0f;
#pragma unroll
    for (int c = 0; c < NCLS; c++) s += expf(v[c] - m);
    float lse = m + logf(s);
#pragma unroll
    for (int c = 0; c < NCLS; c++)
        out[(size_t)n * NCLS + c] = v[c] - lse;
}

extern "C" void kernel_launch(void* const* d_in, const int* in_sizes, int n_in,
                              void* d_out, int out_size) {
    const float* x  = (const float*)d_in[0];
    const int*   ei = (const int*)d_in[1];    // edge_index: int32
    const float* ew = (const float*)d_in[2];
    const float* W1 = (const float*)d_in[3];
    const float* b1 = (const float*)d_in[4];
    const float* W2 = (const float*)d_in[5];
    const float* b2 = (const float*)d_in[6];
    float* out = (float*)d_out;

    const int TB = 256;
    const int nodeGrid  = (N_NODES + TB - 1) / TB;
    const int edgeGrid  = (N_EDGES + TB - 1) / TB;
    const int edge4Grid = (N_EDGES * 4 + TB - 1) / TB;
    const int edge2Grid = (N_EDGES * 2 + TB - 1) / TB;

    k_deg_init<<<nodeGrid, TB>>>();
    k_deg_acc<<<edgeGrid, TB>>>(ei, ew);
    k_gemm1<<<nodeGrid, TB>>>(x, W1);
    k_edge1<<<edge4Grid, TB>>>(ei, ew);
    k_layer2<<<nodeGrid, TB>>>(b1, W2);
    k_edge2<<<edge2Grid, TB>>>(ei, ew);
    k_out<<<nodeGrid, TB>>>(b2, out);
}

// round 6
// speedup vs baseline: 1.2151x; 1.2151x over previous
#include <cuda_runtime.h>
#include <cstdint>

#define N_NODES 100000
#define N_EDGES 3200000
#define D_FEAT  128
#define HIDDEN  16
#define NCLS    7
#define H2PAD   8
#define NB_SCAN ((N_NODES + 1023) / 1024)   // 98 scan blocks

// ---- scratch (static __device__ arrays; no allocation allowed) ----
__device__ float d_dinv[N_NODES];
__device__ float d_g1  [N_NODES * HIDDEN];
__device__ float d_acc1[N_NODES * HIDDEN];
__device__ float d_g2  [N_NODES * H2PAD];
__device__ float d_acc2[N_NODES * H2PAD];
__device__ int   d_count [N_NODES];
__device__ int   d_off   [N_NODES + 1];
__device__ int   d_cursor[N_NODES];
__device__ int   d_btot  [NB_SCAN];
__device__ int   d_boff  [NB_SCAN];
__device__ int2  d_edge_s[N_EDGES];          // dst-sorted {src, w_as_int}

// ---------------- build CSR ----------------
__global__ void k_zero() {
    int n = blockIdx.x * blockDim.x + threadIdx.x;
    if (n < N_NODES) d_count[n] = 0;
}

__global__ void k_hist(const int* __restrict__ ei) {
    int e = blockIdx.x * blockDim.x + threadIdx.x;
    if (e >= N_EDGES) return;
    atomicAdd(&d_count[ei[N_EDGES + e]], 1);
}

__global__ void __launch_bounds__(1024) k_scanA() {
    __shared__ int s[1024];
    int tid = threadIdx.x;
    int i = blockIdx.x * 1024 + tid;
    int v = (i < N_NODES) ? d_count[i] : 0;
    s[tid] = v;
    __syncthreads();
#pragma unroll
    for (int off = 1; off < 1024; off <<= 1) {
        int t = (tid >= off) ? s[tid - off] : 0;
        __syncthreads();
        s[tid] += t;
        __syncthreads();
    }
    if (i < N_NODES) d_off[i] = s[tid] - v;       // exclusive within block
    if (tid == 1023) d_btot[blockIdx.x] = s[1023];
}

__global__ void __launch_bounds__(128) k_scanB() {
    __shared__ int s[128];
    int tid = threadIdx.x;
    int v = (tid < NB_SCAN) ? d_btot[tid] : 0;
    s[tid] = v;
    __syncthreads();
#pragma unroll
    for (int off = 1; off < 128; off <<= 1) {
        int t = (tid >= off) ? s[tid - off] : 0;
        __syncthreads();
        s[tid] += t;
        __syncthreads();
    }
    if (tid < NB_SCAN) d_boff[tid] = s[tid] - v;  // exclusive
}

__global__ void k_scanC() {
    int i = blockIdx.x * blockDim.x + threadIdx.x;
    if (i < N_NODES) {
        int o = d_off[i] + d_boff[i >> 10];
        d_off[i] = o;
        d_cursor[i] = o;
    }
    if (i == 0) d_off[N_NODES] = N_EDGES;
}

__global__ void k_reorder(const int* __restrict__ ei,
                          const float* __restrict__ ew) {
    int e = blockIdx.x * blockDim.x + threadIdx.x;
    if (e >= N_EDGES) return;
    int src = ei[e];
    int dst = ei[N_EDGES + e];
    int pos = atomicAdd(&d_cursor[dst], 1);
    d_edge_s[pos] = make_int2(src, __float_as_int(ew[e]));
}

// ---------------- per-node degree -> dinv (warp per node) ----------------
__global__ void k_deg() {
    int wg = (blockIdx.x * blockDim.x + threadIdx.x) >> 5;
    int lane = threadIdx.x & 31;
    if (wg >= N_NODES) return;
    int start = d_off[wg], end = d_off[wg + 1];
    float s = 0.0f;
    for (int i = start + lane; i < end; i += 32)
        s += __int_as_float(d_edge_s[i].y);
#pragma unroll
    for (int off = 16; off >= 1; off >>= 1)
        s += __shfl_down_sync(0xffffffff, s, off);
    if (lane == 0) d_dinv[wg] = rsqrtf(s + 1.0f);   // +1 self-loop
}

// ---------------- layer 1 projection: g1 = (x @ W1) * dinv ----------------
#define KCHUNK 16
__global__ void __launch_bounds__(256) k_gemm1(const float* __restrict__ x,
                                               const float* __restrict__ W1) {
    __shared__ float sW[D_FEAT * HIDDEN];
    __shared__ float sx[256][KCHUNK + 1];
    for (int i = threadIdx.x; i < D_FEAT * HIDDEN; i += blockDim.x)
        sW[i] = W1[i];

    int tid = threadIdx.x;
    int n0 = blockIdx.x * 256;
    int n  = n0 + tid;
    int nrows = min(256, N_NODES - n0);

    float acc[HIDDEN];
#pragma unroll
    for (int j = 0; j < HIDDEN; j++) acc[j] = 0.0f;

    for (int c = 0; c < D_FEAT / KCHUNK; c++) {
        __syncthreads();
        int nvec = nrows * (KCHUNK / 4);
        for (int idx = tid; idx < nvec; idx += 256) {
            int r = idx >> 2;
            int q = idx & 3;
            float4 v = *(const float4*)(x + (size_t)(n0 + r) * D_FEAT + c * KCHUNK + q * 4);
            sx[r][q * 4 + 0] = v.x;
            sx[r][q * 4 + 1] = v.y;
            sx[r][q * 4 + 2] = v.z;
            sx[r][q * 4 + 3] = v.w;
        }
        __syncthreads();
        if (n < N_NODES) {
#pragma unroll
            for (int kk = 0; kk < KCHUNK; kk++) {
                float v = sx[tid][kk];
                const float* wrow = &sW[(c * KCHUNK + kk) * HIDDEN];
#pragma unroll
                for (int j = 0; j < HIDDEN; j++)
                    acc[j] = fmaf(v, wrow[j], acc[j]);
            }
        }
    }

    if (n >= N_NODES) return;
    float di = d_dinv[n];
    float4* g = (float4*)(d_g1 + (size_t)n * HIDDEN);
#pragma unroll
    for (int q = 0; q < 4; q++)
        g[q] = make_float4(acc[q*4+0]*di, acc[q*4+1]*di,
                           acc[q*4+2]*di, acc[q*4+3]*di);
}

// ---------------- aggregate layer 1 (warp per node, 4 lanes/edge) ----------------
__global__ void k_agg1() {
    int wg = (blockIdx.x * blockDim.x + threadIdx.x) >> 5;
    int lane = threadIdx.x & 31;
    if (wg >= N_NODES) return;
    int start = d_off[wg], end = d_off[wg + 1];
    int q = lane & 3;       // float4 slot within row
    int j = lane >> 2;      // edge slot 0..7
    float4 acc = make_float4(0.f, 0.f, 0.f, 0.f);
    for (int i = start + j; i < end; i += 8) {
        int2 ed = d_edge_s[i];
        float w = __int_as_float(ed.y);
        float4 v = *(const float4*)(d_g1 + (size_t)ed.x * HIDDEN + q * 4);
        acc.x = fmaf(v.x, w, acc.x);
        acc.y = fmaf(v.y, w, acc.y);
        acc.z = fmaf(v.z, w, acc.z);
        acc.w = fmaf(v.w, w, acc.w);
    }
#pragma unroll
    for (int off = 16; off >= 4; off >>= 1) {
        acc.x += __shfl_down_sync(0xffffffff, acc.x, off);
        acc.y += __shfl_down_sync(0xffffffff, acc.y, off);
        acc.z += __shfl_down_sync(0xffffffff, acc.z, off);
        acc.w += __shfl_down_sync(0xffffffff, acc.w, off);
    }
    if (lane < 4) {
        float4 self = *(const float4*)(d_g1 + (size_t)wg * HIDDEN + q * 4);
        acc.x += self.x; acc.y += self.y; acc.z += self.z; acc.w += self.w;
        *(float4*)(d_acc1 + (size_t)wg * HIDDEN + q * 4) = acc;
    }
}

// ---------------- layer-1 epilogue + layer-2 projection ----------------
__global__ void k_layer2(const float* __restrict__ b1,
                         const float* __restrict__ W2) {
    __shared__ float sW[HIDDEN * NCLS];
    __shared__ float sb1[HIDDEN];
    if (threadIdx.x < HIDDEN * NCLS) sW[threadIdx.x] = W2[threadIdx.x];
    if (threadIdx.x < HIDDEN)        sb1[threadIdx.x] = b1[threadIdx.x];
    __syncthreads();

    int n = blockIdx.x * blockDim.x + threadIdx.x;
    if (n >= N_NODES) return;

    float di = d_dinv[n];
    float h[HIDDEN];
    const float4* a = (const float4*)(d_acc1 + (size_t)n * HIDDEN);
#pragma unroll
    for (int q = 0; q < 4; q++) {
        float4 v = a[q];
        h[q*4+0] = fmaxf(v.x * di + sb1[q*4+0], 0.0f);
        h[q*4+1] = fmaxf(v.y * di + sb1[q*4+1], 0.0f);
        h[q*4+2] = fmaxf(v.z * di + sb1[q*4+2], 0.0f);
        h[q*4+3] = fmaxf(v.w * di + sb1[q*4+3], 0.0f);
    }

    float o[H2PAD];
#pragma unroll
    for (int c = 0; c < H2PAD; c++) o[c] = 0.0f;
#pragma unroll
    for (int j = 0; j < HIDDEN; j++) {
#pragma unroll
        for (int c = 0; c < NCLS; c++)
            o[c] = fmaf(h[j], sW[j * NCLS + c], o[c]);
    }

    float4* g = (float4*)(d_g2 + (size_t)n * H2PAD);
#pragma unroll
    for (int q = 0; q < 2; q++)
        g[q] = make_float4(o[q*4+0]*di, o[q*4+1]*di, o[q*4+2]*di, o[q*4+3]*di);
}

// ---------------- aggregate layer 2 (warp per node, 2 lanes/edge) ----------------
__global__ void k_agg2() {
    int wg = (blockIdx.x * blockDim.x + threadIdx.x) >> 5;
    int lane = threadIdx.x & 31;
    if (wg >= N_NODES) return;
    int start = d_off[wg], end = d_off[wg + 1];
    int q = lane & 1;       // float4 slot
    int j = lane >> 1;      // edge slot 0..15
    float4 acc = make_float4(0.f, 0.f, 0.f, 0.f);
    for (int i = start + j; i < end; i += 16) {
        int2 ed = d_edge_s[i];
        float w = __int_as_float(ed.y);
        float4 v = *(const float4*)(d_g2 + (size_t)ed.x * H2PAD + q * 4);
        acc.x = fmaf(v.x, w, acc.x);
        acc.y = fmaf(v.y, w, acc.y);
        acc.z = fmaf(v.z, w, acc.z);
        acc.w = fmaf(v.w, w, acc.w);
    }
#pragma unroll
    for (int off = 16; off >= 2; off >>= 1) {
        acc.x += __shfl_down_sync(0xffffffff, acc.x, off);
        acc.y += __shfl_down_sync(0xffffffff, acc.y, off);
        acc.z += __shfl_down_sync(0xffffffff, acc.z, off);
        acc.w += __shfl_down_sync(0xffffffff, acc.w, off);
    }
    if (lane < 2) {
        float4 self = *(const float4*)(d_g2 + (size_t)wg * H2PAD + q * 4);
        acc.x += self.x; acc.y += self.y; acc.z += self.z; acc.w += self.w;
        *(float4*)(d_acc2 + (size_t)wg * H2PAD + q * 4) = acc;
    }
}

// ---------------- layer-2 epilogue: log_softmax ----------------
__global__ void k_out(const float* __restrict__ b2,
                      float* __restrict__ out) {
    int n = blockIdx.x * blockDim.x + threadIdx.x;
    if (n >= N_NODES) return;
    float di = d_dinv[n];
    float v[NCLS];
    const float4* a = (const float4*)(d_acc2 + (size_t)n * H2PAD);
    float4 p0 = a[0], p1 = a[1];
    v[0] = p0.x * di + b2[0];
    v[1] = p0.y * di + b2[1];
    v[2] = p0.z * di + b2[2];
    v[3] = p0.w * di + b2[3];
    v[4] = p1.x * di + b2[4];
    v[5] = p1.y * di + b2[5];
    v[6] = p1.z * di + b2[6];
    float m = v[0];
#pragma unroll
    for (int c = 1; c < NCLS; c++) m = fmaxf(m, v[c]);
    float s = 0.0f;
#pragma unroll
    for (int c = 0; c < NCLS; c++) s += expf(v[c] - m);
    float lse = m + logf(s);
#pragma unroll
    for (int c = 0; c < NCLS; c++)
        out[(size_t)n * NCLS + c] = v[c] - lse;
}

extern "C" void kernel_launch(void* const* d_in, const int* in_sizes, int n_in,
                              void* d_out, int out_size) {
    const float* x  = (const float*)d_in[0];
    const int*   ei = (const int*)d_in[1];
    const float* ew = (const float*)d_in[2];
    const float* W1 = (const float*)d_in[3];
    const float* b1 = (const float*)d_in[4];
    const float* W2 = (const float*)d_in[5];
    const float* b2 = (const float*)d_in[6];
    float* out = (float*)d_out;

    const int TB = 256;
    const int nodeGrid = (N_NODES + TB - 1) / TB;
    const int edgeGrid = (N_EDGES + TB - 1) / TB;
    const int warpNodeGrid = (N_NODES * 32 + TB - 1) / TB;   // warp per node

    k_zero<<<nodeGrid, TB>>>();
    k_hist<<<edgeGrid, TB>>>(ei);
    k_scanA<<<NB_SCAN, 1024>>>();
    k_scanB<<<1, 128>>>();
    k_scanC<<<nodeGrid, TB>>>();
    k_reorder<<<edgeGrid, TB>>>(ei, ew);
    k_deg<<<warpNodeGrid, TB>>>();
    k_gemm1<<<nodeGrid, TB>>>(x, W1);
    k_agg1<<<warpNodeGrid, TB>>>();
    k_layer2<<<nodeGrid, TB>>>(b1, W2);
    k_agg2<<<warpNodeGrid, TB>>>();
    k_out<<<nodeGrid, TB>>>(b2, out);
}

// round 7
// speedup vs baseline: 1.2326x; 1.0144x over previous
#include <cuda_runtime.h>
#include <cuda_fp16.h>
#include <cstdint>

#define N_NODES 100000
#define N_EDGES 3200000
#define D_FEAT  128
#define HIDDEN  16
#define NCLS    7
#define H2PAD   8
#define NB_SCAN ((N_NODES + 1023) / 1024)   // 98 scan blocks

// ---- scratch (static __device__ arrays; no allocation allowed) ----
__device__ float  d_deg [N_NODES];
__device__ float  d_dinv[N_NODES];
__device__ __half d_g1h [N_NODES * HIDDEN];   // fp16 messages, layer 1
__device__ float  d_acc1[N_NODES * HIDDEN];
__device__ __half d_g2h [N_NODES * H2PAD];    // fp16 messages, layer 2
__device__ float  d_acc2[N_NODES * H2PAD];
__device__ int    d_count [N_NODES];
__device__ int    d_off   [N_NODES + 1];
__device__ int    d_cursor[N_NODES];
__device__ int    d_btot  [NB_SCAN];
__device__ int    d_boff  [NB_SCAN];
__device__ int2   d_edge_s[N_EDGES];          // dst-sorted {src, w_as_int}

// ---------------- init ----------------
__global__ void k_zero() {
    int n = blockIdx.x * blockDim.x + threadIdx.x;
    if (n < N_NODES) { d_count[n] = 0; d_deg[n] = 1.0f; }  // self-loop weight
}

// histogram + weighted degree in one pass
__global__ void k_hist(const int* __restrict__ ei,
                       const float* __restrict__ ew) {
    int e = blockIdx.x * blockDim.x + threadIdx.x;
    if (e >= N_EDGES) return;
    int dst = ei[N_EDGES + e];
    atomicAdd(&d_count[dst], 1);
    atomicAdd(&d_deg[dst], ew[e]);
}

__global__ void __launch_bounds__(1024) k_scanA() {
    __shared__ int s[1024];
    int tid = threadIdx.x;
    int i = blockIdx.x * 1024 + tid;
    int v = (i < N_NODES) ? d_count[i] : 0;
    s[tid] = v;
    __syncthreads();
#pragma unroll
    for (int off = 1; off < 1024; off <<= 1) {
        int t = (tid >= off) ? s[tid - off] : 0;
        __syncthreads();
        s[tid] += t;
        __syncthreads();
    }
    if (i < N_NODES) d_off[i] = s[tid] - v;       // exclusive within block
    if (tid == 1023) d_btot[blockIdx.x] = s[1023];
}

__global__ void __launch_bounds__(128) k_scanB() {
    __shared__ int s[128];
    int tid = threadIdx.x;
    int v = (tid < NB_SCAN) ? d_btot[tid] : 0;
    s[tid] = v;
    __syncthreads();
#pragma unroll
    for (int off = 1; off < 128; off <<= 1) {
        int t = (tid >= off) ? s[tid - off] : 0;
        __syncthreads();
        s[tid] += t;
        __syncthreads();
    }
    if (tid < NB_SCAN) d_boff[tid] = s[tid] - v;  // exclusive
}

__global__ void k_scanC() {
    int i = blockIdx.x * blockDim.x + threadIdx.x;
    if (i < N_NODES) {
        int o = d_off[i] + d_boff[i >> 10];
        d_off[i] = o;
        d_cursor[i] = o;
    }
    if (i == 0) d_off[N_NODES] = N_EDGES;
}

__global__ void k_reorder(const int* __restrict__ ei,
                          const float* __restrict__ ew) {
    int e = blockIdx.x * blockDim.x + threadIdx.x;
    if (e >= N_EDGES) return;
    int src = ei[e];
    int dst = ei[N_EDGES + e];
    int pos = atomicAdd(&d_cursor[dst], 1);
    d_edge_s[pos] = make_int2(src, __float_as_int(ew[e]));
}

// ---------------- layer 1 projection: g1h = half((x @ W1) * dinv) ----------------
#define KCHUNK 16
__global__ void __launch_bounds__(256) k_gemm1(const float* __restrict__ x,
                                               const float* __restrict__ W1) {
    __shared__ float sW[D_FEAT * HIDDEN];
    __shared__ float sx[256][KCHUNK + 1];
    for (int i = threadIdx.x; i < D_FEAT * HIDDEN; i += blockDim.x)
        sW[i] = W1[i];

    int tid = threadIdx.x;
    int n0 = blockIdx.x * 256;
    int n  = n0 + tid;
    int nrows = min(256, N_NODES - n0);

    float acc[HIDDEN];
#pragma unroll
    for (int j = 0; j < HIDDEN; j++) acc[j] = 0.0f;

    for (int c = 0; c < D_FEAT / KCHUNK; c++) {
        __syncthreads();
        int nvec = nrows * (KCHUNK / 4);
        for (int idx = tid; idx < nvec; idx += 256) {
            int r = idx >> 2;
            int q = idx & 3;
            float4 v = *(const float4*)(x + (size_t)(n0 + r) * D_FEAT + c * KCHUNK + q * 4);
            sx[r][q * 4 + 0] = v.x;
            sx[r][q * 4 + 1] = v.y;
            sx[r][q * 4 + 2] = v.z;
            sx[r][q * 4 + 3] = v.w;
        }
        __syncthreads();
        if (n < N_NODES) {
#pragma unroll
            for (int kk = 0; kk < KCHUNK; kk++) {
                float v = sx[tid][kk];
                const float* wrow = &sW[(c * KCHUNK + kk) * HIDDEN];
#pragma unroll
                for (int j = 0; j < HIDDEN; j++)
                    acc[j] = fmaf(v, wrow[j], acc[j]);
            }
        }
    }

    if (n >= N_NODES) return;
    float di = rsqrtf(d_deg[n]);
    d_dinv[n] = di;
    half2* g = (half2*)(d_g1h + (size_t)n * HIDDEN);
#pragma unroll
    for (int p = 0; p < HIDDEN / 2; p++)
        g[p] = __floats2half2_rn(acc[2*p] * di, acc[2*p+1] * di);
}

// ---------------- aggregate layer 1 (warp per node, 4 lanes/edge, 8B gather/lane) ----------------
__global__ void k_agg1() {
    int wg = (blockIdx.x * blockDim.x + threadIdx.x) >> 5;
    int lane = threadIdx.x & 31;
    if (wg >= N_NODES) return;
    int start = d_off[wg], end = d_off[wg + 1];
    int q = lane & 3;       // which 4-half chunk of the 16-half row
    int j = lane >> 2;      // edge slot 0..7
    float4 acc = make_float4(0.f, 0.f, 0.f, 0.f);
    for (int i = start + j; i < end; i += 8) {
        int2 ed = d_edge_s[i];
        float w = __int_as_float(ed.y);
        uint2 pk = *(const uint2*)(d_g1h + (size_t)ed.x * HIDDEN + q * 4);
        float2 lo = __half22float2(*(const half2*)&pk.x);
        float2 hi = __half22float2(*(const half2*)&pk.y);
        acc.x = fmaf(lo.x, w, acc.x);
        acc.y = fmaf(lo.y, w, acc.y);
        acc.z = fmaf(hi.x, w, acc.z);
        acc.w = fmaf(hi.y, w, acc.w);
    }
#pragma unroll
    for (int off = 16; off >= 4; off >>= 1) {
        acc.x += __shfl_down_sync(0xffffffff, acc.x, off);
        acc.y += __shfl_down_sync(0xffffffff, acc.y, off);
        acc.z += __shfl_down_sync(0xffffffff, acc.z, off);
        acc.w += __shfl_down_sync(0xffffffff, acc.w, off);
    }
    if (lane < 4) {
        uint2 pk = *(const uint2*)(d_g1h + (size_t)wg * HIDDEN + q * 4);
        float2 lo = __half22float2(*(const half2*)&pk.x);
        float2 hi = __half22float2(*(const half2*)&pk.y);
        acc.x += lo.x; acc.y += lo.y; acc.z += hi.x; acc.w += hi.y;
        *(float4*)(d_acc1 + (size_t)wg * HIDDEN + q * 4) = acc;
    }
}

// ---------------- layer-1 epilogue + layer-2 projection ----------------
__global__ void k_layer2(const float* __restrict__ b1,
                         const float* __restrict__ W2) {
    __shared__ float sW[HIDDEN * NCLS];
    __shared__ float sb1[HIDDEN];
    if (threadIdx.x < HIDDEN * NCLS) sW[threadIdx.x] = W2[threadIdx.x];
    if (threadIdx.x < HIDDEN)        sb1[threadIdx.x] = b1[threadIdx.x];
    __syncthreads();

    int n = blockIdx.x * blockDim.x + threadIdx.x;
    if (n >= N_NODES) return;

    float di = d_dinv[n];
    float h[HIDDEN];
    const float4* a = (const float4*)(d_acc1 + (size_t)n * HIDDEN);
#pragma unroll
    for (int q = 0; q < 4; q++) {
        float4 v = a[q];
        h[q*4+0] = fmaxf(v.x * di + sb1[q*4+0], 0.0f);
        h[q*4+1] = fmaxf(v.y * di + sb1[q*4+1], 0.0f);
        h[q*4+2] = fmaxf(v.z * di + sb1[q*4+2], 0.0f);
        h[q*4+3] = fmaxf(v.w * di + sb1[q*4+3], 0.0f);
    }

    float o[H2PAD];
#pragma unroll
    for (int c = 0; c < H2PAD; c++) o[c] = 0.0f;   // o[7] stays exactly 0
#pragma unroll
    for (int j = 0; j < HIDDEN; j++) {
#pragma unroll
        for (int c = 0; c < NCLS; c++)
            o[c] = fmaf(h[j], sW[j * NCLS + c], o[c]);
    }

    half2* g = (half2*)(d_g2h + (size_t)n * H2PAD);
#pragma unroll
    for (int p = 0; p < H2PAD / 2; p++)
        g[p] = __floats2half2_rn(o[2*p] * di, o[2*p+1] * di);
}

// ---------------- aggregate layer 2 (warp per node, 2 lanes/edge, 8B gather/lane) ----------------
__global__ void k_agg2() {
    int wg = (blockIdx.x * blockDim.x + threadIdx.x) >> 5;
    int lane = threadIdx.x & 31;
    if (wg >= N_NODES) return;
    int start = d_off[wg], end = d_off[wg + 1];
    int q = lane & 1;       // which 4-half chunk of the 8-half row
    int j = lane >> 1;      // edge slot 0..15
    float4 acc = make_float4(0.f, 0.f, 0.f, 0.f);
    for (int i = start + j; i < end; i += 16) {
        int2 ed = d_edge_s[i];
        float w = __int_as_float(ed.y);
        uint2 pk = *(const uint2*)(d_g2h + (size_t)ed.x * H2PAD + q * 4);
        float2 lo = __half22float2(*(const half2*)&pk.x);
        float2 hi = __half22float2(*(const half2*)&pk.y);
        acc.x = fmaf(lo.x, w, acc.x);
        acc.y = fmaf(lo.y, w, acc.y);
        acc.z = fmaf(hi.x, w, acc.z);
        acc.w = fmaf(hi.y, w, acc.w);
    }
#pragma unroll
    for (int off = 16; off >= 2; off >>= 1) {
        acc.x += __shfl_down_sync(0xffffffff, acc.x, off);
        acc.y += __shfl_down_sync(0xffffffff, acc.y, off);
        acc.z += __shfl_down_sync(0xffffffff, acc.z, off);
        acc.w += __shfl_down_sync(0xffffffff, acc.w, off);
    }
    if (lane < 2) {
        uint2 pk = *(const uint2*)(d_g2h + (size_t)wg * H2PAD + q * 4);
        float2 lo = __half22float2(*(const half2*)&pk.x);
        float2 hi = __half22float2(*(const half2*)&pk.y);
        acc.x += lo.x; acc.y += lo.y; acc.z += hi.x; acc.w += hi.y;
        *(float4*)(d_acc2 + (size_t)wg * H2PAD + q * 4) = acc;
    }
}

// ---------------- layer-2 epilogue: log_softmax ----------------
__global__ void k_out(const float* __restrict__ b2,
                      float* __restrict__ out) {
    int n = blockIdx.x * blockDim.x + threadIdx.x;
    if (n >= N_NODES) return;
    float di = d_dinv[n];
    float v[NCLS];
    const float4* a = (const float4*)(d_acc2 + (size_t)n * H2PAD);
    float4 p0 = a[0], p1 = a[1];
    v[0] = p0.x * di + b2[0];
    v[1] = p0.y * di + b2[1];
    v[2] = p0.z * di + b2[2];
    v[3] = p0.w * di + b2[3];
    v[4] = p1.x * di + b2[4];
    v[5] = p1.y * di + b2[5];
    v[6] = p1.z * di + b2[6];
    float m = v[0];
#pragma unroll
    for (int c = 1; c < NCLS; c++) m = fmaxf(m, v[c]);
    float s = 0.0f;
#pragma unroll
    for (int c = 0; c < NCLS; c++) s += expf(v[c] - m);
    float lse = m + logf(s);
#pragma unroll
    for (int c = 0; c < NCLS; c++)
        out[(size_t)n * NCLS + c] = v[c] - lse;
}

extern "C" void kernel_launch(void* const* d_in, const int* in_sizes, int n_in,
                              void* d_out, int out_size) {
    const float* x  = (const float*)d_in[0];
    const int*   ei = (const int*)d_in[1];
    const float* ew = (const float*)d_in[2];
    const float* W1 = (const float*)d_in[3];
    const float* b1 = (const float*)d_in[4];
    const float* W2 = (const float*)d_in[5];
    const float* b2 = (const float*)d_in[6];
    float* out = (float*)d_out;

    const int TB = 256;
    const int nodeGrid = (N_NODES + TB - 1) / TB;
    const int edgeGrid = (N_EDGES + TB - 1) / TB;
    const int warpNodeGrid = (N_NODES * 32 + TB - 1) / TB;   // warp per node

    k_zero<<<nodeGrid, TB>>>();
    k_hist<<<edgeGrid, TB>>>(ei, ew);
    k_scanA<<<NB_SCAN, 1024>>>();
    k_scanB<<<1, 128>>>();
    k_scanC<<<nodeGrid, TB>>>();
    k_reorder<<<edgeGrid, TB>>>(ei, ew);
    k_gemm1<<<nodeGrid, TB>>>(x, W1);
    k_agg1<<<warpNodeGrid, TB>>>();
    k_layer2<<<nodeGrid, TB>>>(b1, W2);
    k_agg2<<<warpNodeGrid, TB>>>();
    k_out<<<nodeGrid, TB>>>(b2, out);
}